// round 1
// baseline (speedup 1.0000x reference)
#include <cuda_runtime.h>
#include <cuda_bf16.h>

#define NN 50000
#define EE 800000
#define F  128
#define WPAD 132   // padded weight row stride (conflict-free float4 LDS)

// ---------------- scratch (static device allocations, allowed) ----------------
__device__ int   g_cnt[NN];
__device__ int   g_fill[NN];
__device__ int   g_rowptr[NN + 1];
__device__ int   g_csrc[EE];
__device__ float g_cew[EE];
__device__ float g_neigh[(size_t)NN * F];
__device__ float g_h1[(size_t)NN * F];
__device__ float g_h2[(size_t)NN * F];

// ---------------- CSR build ----------------
__global__ void k_zero() {
    int i = blockIdx.x * blockDim.x + threadIdx.x;
    if (i < NN) { g_cnt[i] = 0; g_fill[i] = 0; }
}

__global__ void k_hist(const int* __restrict__ dst) {
    int e = blockIdx.x * blockDim.x + threadIdx.x;
    if (e < EE) atomicAdd(&g_cnt[dst[e]], 1);
}

// single-block Hillis-Steele chunked scan (exclusive prefix over g_cnt)
__global__ void k_scan() {
    __shared__ int sh[1024];
    const int tid = threadIdx.x;
    int carry = 0;
    for (int base = 0; base < NN; base += 1024) {
        int idx = base + tid;
        int x = (idx < NN) ? g_cnt[idx] : 0;
        int orig = x;
        sh[tid] = x; __syncthreads();
        for (int off = 1; off < 1024; off <<= 1) {
            int y = (tid >= off) ? sh[tid - off] : 0;
            __syncthreads();
            sh[tid] += y; __syncthreads();
        }
        if (idx < NN) g_rowptr[idx] = carry + sh[tid] - orig;
        carry += sh[1023];
        __syncthreads();
    }
    if (tid == 0) g_rowptr[NN] = carry;
}

__global__ void k_scatter(const int* __restrict__ src, const int* __restrict__ dst,
                          const float* __restrict__ ew) {
    int e = blockIdx.x * blockDim.x + threadIdx.x;
    if (e < EE) {
        int d = dst[e];
        int p = g_rowptr[d] + atomicAdd(&g_fill[d], 1);
        g_csrc[p] = src[e];
        g_cew[p]  = ew[e];
    }
}

// ---------------- neighbor mean aggregation (gather, warp per node) ----------------
__global__ void k_agg(const float* __restrict__ hin) {
    int v    = (blockIdx.x * blockDim.x + threadIdx.x) >> 5;
    int lane = threadIdx.x & 31;
    if (v >= NN) return;
    int s0 = g_rowptr[v], s1 = g_rowptr[v + 1];
    float4 acc = make_float4(0.f, 0.f, 0.f, 0.f);
    for (int i = s0; i < s1; i++) {
        int   s  = g_csrc[i];
        float wt = g_cew[i];
        const float4 hv = *reinterpret_cast<const float4*>(hin + (size_t)s * F + lane * 4);
        acc.x += wt * hv.x; acc.y += wt * hv.y;
        acc.z += wt * hv.z; acc.w += wt * hv.w;
    }
    int deg = s1 - s0;
    float invd = 1.0f / (float)(deg > 1 ? deg : 1);
    acc.x *= invd; acc.y *= invd; acc.z *= invd; acc.w *= invd;
    *reinterpret_cast<float4*>(g_neigh + (size_t)v * F + lane * 4) = acc;
}

// ---------------- fused SAGE GEMM: out = relu(h@Ws + neigh@Wn + b) ----------------
// 512 threads = 4 groups of 128. Each group owns 8 nodes (2 chunks of 4).
// Thread j of a group computes output feature j for its 4 current nodes.
// Weights live transposed+padded in smem so the k-loop uses float4 LDS.
template <bool HN>
__global__ void __launch_bounds__(512, 1)
k_sage(const float* __restrict__ hin, const float* __restrict__ ws,
       const float* __restrict__ wn, const float* __restrict__ b,
       float* __restrict__ hout) {
    extern __shared__ float sm[];
    float* s_ws = sm;                    // [128][WPAD] transposed
    float* s_wn = sm + F * WPAD;         // [128][WPAD] transposed
    float* s_h  = sm + 2 * F * WPAD;     // [4 groups][4 nodes][128]
    float* s_n  = s_h + 4 * 4 * F;       // same

    const int tid = threadIdx.x;

    // load + transpose weights (w[k][j] -> s[j*WPAD + k])
    for (int i = tid; i < F * F / 4; i += blockDim.x) {
        int k = i >> 5;
        int j = (i & 31) * 4;
        float4 v = reinterpret_cast<const float4*>(ws)[i];
        s_ws[(j + 0) * WPAD + k] = v.x;
        s_ws[(j + 1) * WPAD + k] = v.y;
        s_ws[(j + 2) * WPAD + k] = v.z;
        s_ws[(j + 3) * WPAD + k] = v.w;
        if (HN) {
            float4 u = reinterpret_cast<const float4*>(wn)[i];
            s_wn[(j + 0) * WPAD + k] = u.x;
            s_wn[(j + 1) * WPAD + k] = u.y;
            s_wn[(j + 2) * WPAD + k] = u.z;
            s_wn[(j + 3) * WPAD + k] = u.w;
        }
    }

    const int g = tid >> 7;        // group 0..3
    const int j = tid & 127;       // output feature
    const float bj = b[j];
    float* gh = s_h + g * (4 * F);
    float* gn = s_n + g * (4 * F);
    const int nodeBase = blockIdx.x * 32 + g * 8;

    for (int c = 0; c < 2; c++) {
        const int v0 = nodeBase + c * 4;
        __syncthreads();   // weights done (c==0) / prev chunk's rows consumed (c==1)
        {
            int rr = j >> 5;
            int cc = (j & 31) * 4;
            int v  = v0 + rr;
            float4 hv = make_float4(0.f, 0.f, 0.f, 0.f);
            float4 nv = make_float4(0.f, 0.f, 0.f, 0.f);
            if (v < NN) {
                hv = *reinterpret_cast<const float4*>(hin + (size_t)v * F + cc);
                if (HN) nv = *reinterpret_cast<const float4*>(g_neigh + (size_t)v * F + cc);
            }
            *reinterpret_cast<float4*>(gh + rr * F + cc) = hv;
            if (HN) *reinterpret_cast<float4*>(gn + rr * F + cc) = nv;
        }
        __syncthreads();

        float a0 = bj, a1 = bj, a2 = bj, a3 = bj;
        const float* wr = s_ws + j * WPAD;
        const float* nr = s_wn + j * WPAD;
#pragma unroll 4
        for (int k = 0; k < F; k += 4) {
            float4 w4 = *reinterpret_cast<const float4*>(wr + k);
            float4 h0 = *reinterpret_cast<const float4*>(gh + 0 * F + k);
            float4 h1 = *reinterpret_cast<const float4*>(gh + 1 * F + k);
            float4 h2 = *reinterpret_cast<const float4*>(gh + 2 * F + k);
            float4 h3 = *reinterpret_cast<const float4*>(gh + 3 * F + k);
            a0 += h0.x * w4.x + h0.y * w4.y + h0.z * w4.z + h0.w * w4.w;
            a1 += h1.x * w4.x + h1.y * w4.y + h1.z * w4.z + h1.w * w4.w;
            a2 += h2.x * w4.x + h2.y * w4.y + h2.z * w4.z + h2.w * w4.w;
            a3 += h3.x * w4.x + h3.y * w4.y + h3.z * w4.z + h3.w * w4.w;
            if (HN) {
                float4 u4 = *reinterpret_cast<const float4*>(nr + k);
                float4 n0 = *reinterpret_cast<const float4*>(gn + 0 * F + k);
                float4 n1 = *reinterpret_cast<const float4*>(gn + 1 * F + k);
                float4 n2 = *reinterpret_cast<const float4*>(gn + 2 * F + k);
                float4 n3 = *reinterpret_cast<const float4*>(gn + 3 * F + k);
                a0 += n0.x * u4.x + n0.y * u4.y + n0.z * u4.z + n0.w * u4.w;
                a1 += n1.x * u4.x + n1.y * u4.y + n1.z * u4.z + n1.w * u4.w;
                a2 += n2.x * u4.x + n2.y * u4.y + n2.z * u4.z + n2.w * u4.w;
                a3 += n3.x * u4.x + n3.y * u4.y + n3.z * u4.z + n3.w * u4.w;
            }
        }
        a0 = fmaxf(a0, 0.f); a1 = fmaxf(a1, 0.f);
        a2 = fmaxf(a2, 0.f); a3 = fmaxf(a3, 0.f);
        if (v0 + 0 < NN) hout[(size_t)(v0 + 0) * F + j] = a0;
        if (v0 + 1 < NN) hout[(size_t)(v0 + 1) * F + j] = a1;
        if (v0 + 2 < NN) hout[(size_t)(v0 + 2) * F + j] = a2;
        if (v0 + 3 < NN) hout[(size_t)(v0 + 3) * F + j] = a3;
    }
}

// ---------------- final projection: out[v] = h[v] . w2 + b2 ----------------
__global__ void k_dot(const float* __restrict__ h, const float* __restrict__ w2,
                      const float* __restrict__ b2, float* __restrict__ out) {
    int v    = (blockIdx.x * blockDim.x + threadIdx.x) >> 5;
    int lane = threadIdx.x & 31;
    if (v >= NN) return;
    float4 hv = *reinterpret_cast<const float4*>(h + (size_t)v * F + lane * 4);
    float4 wv = *reinterpret_cast<const float4*>(w2 + lane * 4);
    float s = hv.x * wv.x + hv.y * wv.y + hv.z * wv.z + hv.w * wv.w;
#pragma unroll
    for (int o = 16; o; o >>= 1) s += __shfl_xor_sync(0xffffffffu, s, o);
    if (lane == 0) out[v] = s + b2[0];
}

// ---------------- launch ----------------
extern "C" void kernel_launch(void* const* d_in, const int* in_sizes, int n_in,
                              void* d_out, int out_size) {
    const float* inputs = (const float*)d_in[0];
    const float* ew     = (const float*)d_in[1];
    const int*   src    = (const int*)d_in[2];
    const int*   dst    = (const int*)d_in[3];
    const float* ws1 = (const float*)d_in[4];
    const float* wn1 = (const float*)d_in[5];
    const float* b1  = (const float*)d_in[6];
    const float* ws2 = (const float*)d_in[7];
    const float* wn2 = (const float*)d_in[8];
    const float* b2  = (const float*)d_in[9];
    const float* ws3 = (const float*)d_in[10];
    const float* wn3 = (const float*)d_in[11];
    const float* b3  = (const float*)d_in[12];
    const float* wl1 = (const float*)d_in[13];
    const float* bl1 = (const float*)d_in[14];
    const float* wl2 = (const float*)d_in[15];
    const float* bl2 = (const float*)d_in[16];
    float* out = (float*)d_out;

    float *h1, *h2;
    cudaGetSymbolAddress((void**)&h1, g_h1);
    cudaGetSymbolAddress((void**)&h2, g_h2);

    const size_t smem = (size_t)(2 * F * WPAD + 2 * 4 * 4 * F) * sizeof(float); // 151552 B
    cudaFuncSetAttribute(k_sage<true>,  cudaFuncAttributeMaxDynamicSharedMemorySize, (int)smem);
    cudaFuncSetAttribute(k_sage<false>, cudaFuncAttributeMaxDynamicSharedMemorySize, (int)smem);

    const int TB = 256;
    // CSR build (once per launch; reused by all 3 layers)
    k_zero<<<(NN + TB - 1) / TB, TB>>>();
    k_hist<<<(EE + TB - 1) / TB, TB>>>(dst);
    k_scan<<<1, 1024>>>();
    k_scatter<<<(EE + TB - 1) / TB, TB>>>(src, dst, ew);

    const int aggBlocks  = (NN * 32 + TB - 1) / TB;   // warp per node
    const int sageBlocks = (NN + 31) / 32;            // 32 nodes per block

    // layer 1: inputs -> h1
    k_agg<<<aggBlocks, TB>>>(inputs);
    k_sage<true><<<sageBlocks, 512, smem>>>(inputs, ws1, wn1, b1, h1);
    // layer 2: h1 -> h2
    k_agg<<<aggBlocks, TB>>>(h1);
    k_sage<true><<<sageBlocks, 512, smem>>>(h1, ws2, wn2, b2, h2);
    // layer 3: h2 -> h1
    k_agg<<<aggBlocks, TB>>>(h2);
    k_sage<true><<<sageBlocks, 512, smem>>>(h2, ws3, wn3, b3, h1);
    // lin1: h1 -> h2 (self path only, relu)
    k_sage<false><<<sageBlocks, 512, smem>>>(h1, wl1, nullptr, bl1, h2);
    // lin2: h2 -> out
    k_dot<<<aggBlocks, TB>>>(h2, wl2, bl2, out);
}